// round 1
// baseline (speedup 1.0000x reference)
#include <cuda_runtime.h>
#include <cstdint>

// Problem constants
#define DIMC   512
#define HEADSC 8
#define NTOK   64          // tokens per window (8x8)
#define BWIN   2048        // number of windows (32*64)
#define MROWS  (BWIN*NTOK) // 131072
#define PER_LAT 225

// ---------------- scratch (static device memory; allocation is forbidden) ----
__device__ float g_q [BWIN*HEADSC*NTOK*64];  // [B][H][N][D], q pre-scaled by 0.125
__device__ float g_k [BWIN*HEADSC*NTOK*64];
__device__ float g_v [BWIN*HEADSC*NTOK*64];
__device__ float g_ao[(size_t)MROWS*DIMC];   // attention output, row-major [M,512]

// ---------------- tf32 helpers ----------------------------------------------
__device__ __forceinline__ uint32_t f2tf(float x){
    uint32_t r; asm volatile("cvt.rna.tf32.f32 %0, %1;" : "=r"(r) : "f"(x)); return r;
}
__device__ __forceinline__ void mma8(float* c, const uint32_t* a, const uint32_t* b){
    asm volatile(
      "mma.sync.aligned.m16n8k8.row.col.f32.tf32.tf32.f32 "
      "{%0,%1,%2,%3}, {%4,%5,%6,%7}, {%8,%9}, {%0,%1,%2,%3};"
      : "+f"(c[0]), "+f"(c[1]), "+f"(c[2]), "+f"(c[3])
      : "r"(a[0]), "r"(a[1]), "r"(a[2]), "r"(a[3]), "r"(b[0]), "r"(b[1]));
}

// ---------------- GEMM: C[M,N] = A[M,K] * W[N,K]^T + bias[N] -----------------
// MODE 0: QKV epilogue -> scatter to g_q/g_k/g_v (q scaled by 0.125)
// MODE 1: plain epilogue -> out[r*512 + c]
// Block tile 128x128x32, 256 threads (8 warps as 2(M) x 4(N), warp tile 64x32).
template<int MODE>
__global__ void __launch_bounds__(256)
gemm_tf32(const float* __restrict__ A, const float* __restrict__ W,
          const float* __restrict__ bias, float* __restrict__ out, int K)
{
    __shared__ uint32_t As[128*36];   // stride 36: banks (36g+t)%32 = 4g+t, conflict-free
    __shared__ uint32_t Bs[128*36];

    const int tid  = threadIdx.x;
    const int n0   = blockIdx.x * 128;   // n fast so weight panels stay L2-resident
    const int m0   = blockIdx.y * 128;
    const int lane = tid & 31;
    const int wid  = tid >> 5;
    const int g    = lane >> 2;
    const int t4   = lane & 3;
    const int wm   = (wid & 1) * 64;
    const int wn   = (wid >> 1) * 32;

    float acc[4][4][4];
    #pragma unroll
    for (int i=0;i<4;i++)
      #pragma unroll
      for (int j=0;j<4;j++)
        #pragma unroll
        for (int e=0;e<4;e++) acc[i][j][e] = 0.f;

    const int lrow = tid >> 3;          // 0..31
    const int lcol = (tid & 7) * 4;     // 0..28
    const float* Ap = A + (size_t)(m0 + lrow) * K + lcol;
    const float* Wp = W + (size_t)(n0 + lrow) * K + lcol;

    float4 ra[4], rb[4];
    #pragma unroll
    for (int p=0;p<4;p++){
        ra[p] = *(const float4*)(Ap + (size_t)p*32*K);
        rb[p] = *(const float4*)(Wp + (size_t)p*32*K);
    }

    const int KT = K >> 5;
    for (int kt = 0; kt < KT; kt++){
        // convert (rna!) + store staged tile
        #pragma unroll
        for (int p=0;p<4;p++){
            *(uint4*)&As[(lrow+32*p)*36 + lcol] =
                make_uint4(f2tf(ra[p].x), f2tf(ra[p].y), f2tf(ra[p].z), f2tf(ra[p].w));
            *(uint4*)&Bs[(lrow+32*p)*36 + lcol] =
                make_uint4(f2tf(rb[p].x), f2tf(rb[p].y), f2tf(rb[p].z), f2tf(rb[p].w));
        }
        __syncthreads();
        if (kt + 1 < KT){
            const float* An = Ap + (kt+1)*32;
            const float* Wn = Wp + (kt+1)*32;
            #pragma unroll
            for (int p=0;p<4;p++){
                ra[p] = *(const float4*)(An + (size_t)p*32*K);
                rb[p] = *(const float4*)(Wn + (size_t)p*32*K);
            }
        }
        #pragma unroll
        for (int ks=0; ks<4; ks++){
            const int kc = ks*8 + t4;
            uint32_t af[4][4], bf[4][2];
            #pragma unroll
            for (int i=0;i<4;i++){
                const int r = wm + i*16 + g;
                af[i][0] = As[r*36 + kc];
                af[i][1] = As[(r+8)*36 + kc];
                af[i][2] = As[r*36 + kc + 4];
                af[i][3] = As[(r+8)*36 + kc + 4];
            }
            #pragma unroll
            for (int j=0;j<4;j++){
                const int n = wn + j*8 + g;
                bf[j][0] = Bs[n*36 + kc];
                bf[j][1] = Bs[n*36 + kc + 4];
            }
            #pragma unroll
            for (int i=0;i<4;i++)
                #pragma unroll
                for (int j=0;j<4;j++)
                    mma8(acc[i][j], af[i], bf[j]);
        }
        __syncthreads();
    }

    // epilogue. c-frag: e0:(g,2t) e1:(g,2t+1) e2:(g+8,2t) e3:(g+8,2t+1)
    #pragma unroll
    for (int i=0;i<4;i++){
        const int r0 = m0 + wm + i*16 + g;
        #pragma unroll
        for (int j=0;j<4;j++){
            const int c0 = n0 + wn + j*8 + 2*t4;
            #pragma unroll
            for (int e=0;e<4;e++){
                const int r = r0 + (e >> 1) * 8;
                const int c = c0 + (e & 1);
                float v = acc[i][j][e] + bias[c];
                if (MODE == 0){
                    const int s  = c >> 9;
                    const int hh = (c >> 6) & 7;
                    const int d  = c & 63;
                    const int bq = r >> 6;
                    const int t  = r & 63;
                    const int off = (((bq*8 + hh)*64 + t) << 6) + d;
                    if (s == 0)      g_q[off] = v * 0.125f;  // fold 1/sqrt(64)
                    else if (s == 1) g_k[off] = v;
                    else             g_v[off] = v;
                } else {
                    out[(size_t)r * 512 + c] = v;
                }
            }
        }
    }
}

// ---------------- fused attention per (window b, head h) ---------------------
// 128 threads = 4 warps; warp w owns S/O rows [16w, 16w+16).
// bias computed analytically: idx2d(r,c) = ((r>>3)-(c>>3)+7)*15 + ((r&7)-(c&7)+7)
// table slab for (lat,h) staged to SMEM (225 floats).
#define ATTN_SMEM_WORDS (4*64*68 + 240)
__global__ void __launch_bounds__(128)
attn_kernel(const float* __restrict__ btab, float* __restrict__ attno)
{
    extern __shared__ uint32_t smw[];
    uint32_t* sq   = smw;              // [64][68] tf32
    uint32_t* sk   = sq  + 64*68;
    uint32_t* svT  = sk  + 64*68;      // V transposed: [d][m]
    uint32_t* sp   = svT + 64*68;      // P (tf32 bits)
    float*    sbias = (float*)(sp + 64*68);

    const int bh  = blockIdx.x;
    const int b   = bh >> 3;
    const int h   = bh & 7;
    const int lat = b >> 6;
    const int tid = threadIdx.x;
    const int lane = tid & 31;
    const int w   = tid >> 5;
    const int g   = lane >> 2;
    const int t4  = lane & 3;
    const int R0  = w * 16;

    const float* qg = g_q + (size_t)bh * 4096;
    const float* kg = g_k + (size_t)bh * 4096;
    const float* vg = g_v + (size_t)bh * 4096;

    #pragma unroll
    for (int p=0;p<8;p++){
        const int idx = tid + p*128;         // 0..1023
        const int row = idx >> 4;
        const int c4  = (idx & 15) * 4;
        float4 q4 = *(const float4*)(qg + row*64 + c4);
        *(uint4*)&sq[row*68 + c4] = make_uint4(f2tf(q4.x), f2tf(q4.y), f2tf(q4.z), f2tf(q4.w));
        float4 k4 = *(const float4*)(kg + row*64 + c4);
        *(uint4*)&sk[row*68 + c4] = make_uint4(f2tf(k4.x), f2tf(k4.y), f2tf(k4.z), f2tf(k4.w));
        float4 v4 = *(const float4*)(vg + row*64 + c4);
        svT[(c4+0)*68 + row] = f2tf(v4.x);
        svT[(c4+1)*68 + row] = f2tf(v4.y);
        svT[(c4+2)*68 + row] = f2tf(v4.z);
        svT[(c4+3)*68 + row] = f2tf(v4.w);
    }
    for (int i = tid; i < PER_LAT; i += 128)
        sbias[i] = btab[(lat*PER_LAT + i)*8 + h];
    __syncthreads();

    // ---- S = (Q*scale) K^T ----
    float sacc[8][4];
    #pragma unroll
    for (int j=0;j<8;j++){ sacc[j][0]=0.f; sacc[j][1]=0.f; sacc[j][2]=0.f; sacc[j][3]=0.f; }
    #pragma unroll
    for (int ks=0; ks<8; ks++){
        const int kc = ks*8 + t4;
        uint32_t a[4];
        a[0] = sq[(R0+g  )*68 + kc];
        a[1] = sq[(R0+g+8)*68 + kc];
        a[2] = sq[(R0+g  )*68 + kc + 4];
        a[3] = sq[(R0+g+8)*68 + kc + 4];
        #pragma unroll
        for (int j=0;j<8;j++){
            uint32_t bf[2];
            bf[0] = sk[(j*8+g)*68 + kc];
            bf[1] = sk[(j*8+g)*68 + kc + 4];
            mma8(sacc[j], a, bf);
        }
    }

    // ---- bias + row softmax + write P (tf32) ----
    #pragma unroll
    for (int rr=0; rr<2; rr++){
        const int r   = R0 + g + rr*8;
        const int rR  = r >> 3, rC = r & 7;
        float tmp[16];
        float mx = -1e30f;
        #pragma unroll
        for (int j=0;j<8;j++){
            #pragma unroll
            for (int e=0;e<2;e++){
                const int c  = j*8 + 2*t4 + e;
                const int ib = (rR - (c>>3) + 7)*15 + (rC - (c&7) + 7);
                const float s = sacc[j][rr*2+e] + sbias[ib];
                tmp[j*2+e] = s;
                mx = fmaxf(mx, s);
            }
        }
        mx = fmaxf(mx, __shfl_xor_sync(0xffffffffu, mx, 1));
        mx = fmaxf(mx, __shfl_xor_sync(0xffffffffu, mx, 2));
        float sum = 0.f;
        #pragma unroll
        for (int i=0;i<16;i++){ tmp[i] = __expf(tmp[i]-mx); sum += tmp[i]; }
        sum += __shfl_xor_sync(0xffffffffu, sum, 1);
        sum += __shfl_xor_sync(0xffffffffu, sum, 2);
        const float rinv = 1.f / sum;
        #pragma unroll
        for (int j=0;j<8;j++)
            #pragma unroll
            for (int e=0;e<2;e++){
                const int c = j*8 + 2*t4 + e;
                sp[r*68 + c] = f2tf(tmp[j*2+e] * rinv);
            }
    }
    __syncwarp();   // own warp wrote & reads only its own 16 rows of P

    // ---- O = P V ----
    float oacc[8][4];
    #pragma unroll
    for (int j=0;j<8;j++){ oacc[j][0]=0.f; oacc[j][1]=0.f; oacc[j][2]=0.f; oacc[j][3]=0.f; }
    #pragma unroll
    for (int ks=0; ks<8; ks++){
        const int kc = ks*8 + t4;
        uint32_t a[4];
        a[0] = sp[(R0+g  )*68 + kc];
        a[1] = sp[(R0+g+8)*68 + kc];
        a[2] = sp[(R0+g  )*68 + kc + 4];
        a[3] = sp[(R0+g+8)*68 + kc + 4];
        #pragma unroll
        for (int j=0;j<8;j++){
            uint32_t bf[2];
            bf[0] = svT[(j*8+g)*68 + kc];      // V[k][d] via transposed store
            bf[1] = svT[(j*8+g)*68 + kc + 4];
            mma8(oacc[j], a, bf);
        }
    }

    // write O -> attno[(b*64 + r)*512 + h*64 + d]
    float* ob = attno + (size_t)b * 64 * 512 + h * 64;
    #pragma unroll
    for (int j=0;j<8;j++){
        const int c0 = j*8 + 2*t4;
        const int r  = R0 + g;
        ob[(size_t)r*512     + c0    ] = oacc[j][0];
        ob[(size_t)r*512     + c0 + 1] = oacc[j][1];
        ob[(size_t)(r+8)*512 + c0    ] = oacc[j][2];
        ob[(size_t)(r+8)*512 + c0 + 1] = oacc[j][3];
    }
}

// ---------------- launch -----------------------------------------------------
extern "C" void kernel_launch(void* const* d_in, const int* in_sizes, int n_in,
                              void* d_out, int out_size)
{
    const float* x     = (const float*)d_in[0];
    const float* wqkv  = (const float*)d_in[1];
    const float* bqkv  = (const float*)d_in[2];
    const float* wproj = (const float*)d_in[3];
    const float* bproj = (const float*)d_in[4];
    const float* btab  = (const float*)d_in[5];
    // d_in[6] = rel_idx: unused — computed analytically in-kernel.
    float* out = (float*)d_out;

    float* gao_ptr = nullptr;
    cudaGetSymbolAddress((void**)&gao_ptr, g_ao);

    const int attn_smem = ATTN_SMEM_WORDS * 4;   // 70592 B
    cudaFuncSetAttribute(attn_kernel, cudaFuncAttributeMaxDynamicSharedMemorySize, attn_smem);

    // QKV GEMM: M=131072, N=1536, K=512
    gemm_tf32<0><<<dim3(12, 1024), 256>>>(x, wqkv, bqkv, nullptr, 512);
    // attention: one block per (window, head)
    attn_kernel<<<BWIN*HEADSC, 128, attn_smem>>>(btab, gao_ptr);
    // projection GEMM: M=131072, N=512, K=512
    gemm_tf32<1><<<dim3(4, 1024), 256>>>(gao_ptr, wproj, bproj, out, 512);
}